// round 13
// baseline (speedup 1.0000x reference)
#include <cuda_runtime.h>

#define Bn 32
#define Nn 4096
#define Kn 16
#define PPB 16                   // points per block
#define NBLK (Nn / PPB)          // 256 blocks per batch
#define GRIDA (Bn * NBLK)        // 8192 blocks x 256 threads (one (point,k) per thread)

// Deterministic scratch (no allocations allowed)
__device__ float g_comb[GRIDA];               // weighted rec partial per block
__device__ float g_col2[512 * NBLK];          // col partials: [(b*16+k)][block_in_batch]
__device__ unsigned int g_count = 0;

__device__ __forceinline__ float flog2(float x) {
    float y; asm("lg2.approx.f32 %0, %1;" : "=f"(y) : "f"(x)); return y;
}
__device__ __forceinline__ float fexp2(float x) {
    float y; asm("ex2.approx.f32 %0, %1;" : "=f"(y) : "f"(x)); return y;
}

__global__ __launch_bounds__(256) void loss_fused_kernel(
    const float* __restrict__ pc, const float* __restrict__ normals,
    const float* __restrict__ randn, const float* __restrict__ scale,
    const float* __restrict__ shapes, const float* __restrict__ rotate,
    const float* __restrict__ pam, const float* __restrict__ assign,
    const float* __restrict__ exist, const float* __restrict__ mu,
    const float* __restrict__ logvar, const float* __restrict__ trans,
    float* __restrict__ out)
{
    // sP stride 20: [0-8]=R, [9-11]=scale, [12]=he0,[13]=he1,[14]=he01,[15-17]=ncc=-R^T mean
    __shared__ __align__(16) float sP[Kn * 20];
    __shared__ float sM[Kn * 3];
    __shared__ __align__(16) float sPt[PPB * 8];   // px,py,pz,nx,ny,nz,rn0,pad
    __shared__ float sAk[256];
    __shared__ float srec[8];
    __shared__ float sfin[512];
    __shared__ bool  isLast;

    const int blk   = blockIdx.x;
    const int b     = blk >> 8;          // batch
    const int jb    = blk & 255;         // block within batch
    const int nbase = jb * PPB;
    const int t     = threadIdx.x;
    const int lane  = t & 31;
    const int warp  = t >> 5;
    const int p     = t >> 4;            // local point 0..15
    const int k     = t & 15;            // superquadric id

    // --- stage parameters + point data + assign weights ---
    if (t < 144) sP[(t / 9) * 20 + (t % 9)]      = rotate[b * 144 + t];
    if (t < 48)  sP[(t / 3) * 20 + 9 + (t % 3)]  = scale [b * 48  + t];
    if (t < 32)  sP[(t / 2) * 20 + 12 + (t & 1)] = 0.5f * shapes[b * 32 + t];
    if (t < 48)  sM[t]                           = pam   [b * 48  + t];

    if (t < 48)  sPt[(t / 3) * 8 + (t % 3)] = pc[((size_t)b * Nn + nbase) * 3 + t];
    if (t >= 64 && t < 112) {
        const int i = t - 64;
        sPt[(i / 3) * 8 + 3 + (i % 3)] = normals[((size_t)b * Nn + nbase) * 3 + i];
    }
    if (t >= 128 && t < 144)
        sPt[(t - 128) * 8 + 6] = randn[(size_t)b * Nn + nbase + (t - 128)] * 0.01f;

    // ak: perfectly coalesced (address = base + t)
    const float ak = assign[((size_t)b * Nn + nbase) * 16 + t];
    sAk[t] = ak;
    __syncthreads();

    // ncc = -(R^T mean); he01 = he0 - he1
    if (t < 48) {
        const int kk = t / 3, i = t % 3;
        const float* R = sP + kk * 20;
        const float* m = sM + kk * 3;
        sP[kk * 20 + 15 + i] = -(R[i] * m[0] + R[3 + i] * m[1] + R[6 + i] * m[2]);
    } else if (t >= 64 && t < 80) {
        const int kk = t - 64;
        sP[kk * 20 + 14] = sP[kk * 20 + 12] - sP[kk * 20 + 13];
    }
    __syncthreads();

    // --- one (point, k) item ---
    const float4* Pv = reinterpret_cast<const float4*>(sP + k * 20);
    const float4 f0v = Pv[0];   // R0 R1 R2 R3
    const float4 f1v = Pv[1];   // R4 R5 R6 R7
    const float4 f2v = Pv[2];   // R8 s0 s1 s2
    const float4 f3v = Pv[3];   // he0 he1 he01 ncc0
    const float ncc1 = sP[k * 20 + 16];
    const float ncc2 = sP[k * 20 + 17];
    const float R0 = f0v.x, R1 = f0v.y, R2 = f0v.z, R3 = f0v.w;
    const float R4 = f1v.x, R5 = f1v.y, R6 = f1v.z, R7 = f1v.w;
    const float R8 = f2v.x, s0 = f2v.y, s1 = f2v.z, s2 = f2v.w;
    const float he0 = f3v.x, he1 = f3v.y, he01 = f3v.z, ncc0 = f3v.w;

    const float* pt = sPt + p * 8;
    const float px = pt[0], py = pt[1], pz = pt[2];
    const float nx = pt[3], ny = pt[4], nz = pt[5];
    const float rn0 = pt[6];    // randn * 0.01 (raw normals used: argmax is scale-invariant)

    // pci = R^T pc - R^T mean
    const float c0 = fmaf(R0, px, fmaf(R3, py, fmaf(R6, pz, ncc0)));
    const float c1 = fmaf(R1, px, fmaf(R4, py, fmaf(R7, pz, ncc1)));
    const float c2 = fmaf(R2, px, fmaf(R5, py, fmaf(R8, pz, ncc2)));
    // w = R^T n_raw
    const float w0 = fmaf(R0, nx, fmaf(R3, ny, R6 * nz));
    const float w1 = fmaf(R1, nx, fmaf(R4, ny, R7 * nz));
    const float w2 = fmaf(R2, nx, fmaf(R5, ny, R8 * nz));
    // psi = pci + rn0 * w   (rn0 * w == noise * R^T normals)
    const float q0 = fmaf(rn0, w0, c0);
    const float q1 = fmaf(rn0, w1, c1);
    const float q2 = fmaf(rn0, w2, c2);

    // branchless argmax + override (ties -> lowest axis, matches jnp face order)
    const float a0 = fabsf(w0), a1 = fabsf(w1), a2 = fabsf(w2);
    const bool g0 = (a0 >= a1) & (a0 >= a2);
    const bool g1 = (!g0) & (a1 >= a2);
    const bool g2 = !(g0 | g1);
    const float p0 = g0 ? copysignf(s0, w0) : fminf(fmaxf(q0, -s0), s0);
    const float p1 = g1 ? copysignf(s1, w1) : fminf(fmaxf(q1, -s1), s1);
    const float p2 = g2 ? copysignf(s2, w2) : fminf(fmaxf(q2, -s2), s2);

    // log-domain superquadric surface point
    const float p0sq = fmaf(p0, p0, 1e-30f);
    const float p1sq = fmaf(p1, p1, 1e-30f);
    const float p2sq = fmaf(p2, p2, 1e-30f);
    const float r2   = p0sq + p1sq;
    const float rho2 = r2 + p2sq;

    const float Lr = flog2(r2);
    const float Lh = flog2(rho2);
    const float L0 = flog2(p0sq);
    const float L1 = flog2(p1sq);
    const float L2 = flog2(p2sq);

    const float hLh = he0 * Lh;
    const float u   = fmaf(he01, Lr, -hLh);
    const float X = copysignf(s0 * fexp2(fmaf(he1, L0, u)), p0);
    const float Y = copysignf(s1 * fexp2(fmaf(he1, L1, u)), p1);
    const float Z = copysignf(s2 * fexp2(fmaf(he0, L2, -hLh)), p2);

    const float dx = X - c0, dy = Y - c1, dz = Z - c2;
    float v = fmaf(dx, dx, fmaf(dy, dy, dz * dz)) * ak;

    // --- block reductions (deterministic) ---
    #pragma unroll
    for (int off = 16; off; off >>= 1)
        v += __shfl_down_sync(0xffffffffu, v, off);
    if (lane == 0) srec[warp] = v;
    __syncthreads();

    if (t == 0) {
        float s = 0.f;
        #pragma unroll
        for (int w = 0; w < 8; w++) s += srec[w];
        g_comb[blk] = s * (1.0f / (32.f * 4096.f));   // W_REC / (B*N)
    }
    if (t < Kn) {
        float s = 0.f;
        #pragma unroll
        for (int i = 0; i < 16; i++) s += sAk[t + 16 * i];
        g_col2[(b * 16 + t) * NBLK + jb] = s;
    }

    // --- last-block-done: fused final reduction ---
    __threadfence();
    __syncthreads();
    if (t == 0) {
        unsigned int c = atomicAdd(&g_count, 1u);
        isLast = (c == GRIDA - 1);
    }
    __syncthreads();
    if (!isLast) return;
    __threadfence();

    float acc = 0.f;

    // REC: sum of 8192 weighted partials (contiguous float4)
    {
        const float4* gc = reinterpret_cast<const float4*>(g_comb);
        #pragma unroll
        for (int i = 0; i < 8; i++) {
            const float4 vv = gc[t + 256 * i];
            acc += (vv.x + vv.y) + (vv.z + vv.w);
        }
    }

    // cs for 512 (b,k) pairs: 2 per thread; each pair is 256 contiguous floats
    #pragma unroll
    for (int pi2 = 0; pi2 < 2; pi2++) {
        const int pr = t + 256 * pi2;
        const float4* gp = reinterpret_cast<const float4*>(g_col2 + (size_t)pr * NBLK);
        float cs = 0.f;
        #pragma unroll
        for (int i = 0; i < NBLK / 4; i++) {
            const float4 vv = gp[i];
            cs += (vv.x + vv.y) + (vv.z + vv.w);
        }
        sfin[pr] = sqrtf(cs * (1.f / 4096.f) + 0.01f);
        // EXT: BCE-with-logits (weight 0.01)
        const float l  = exist[pr];
        const float gt = (cs > 24.f) ? 1.f : 0.f;
        acc += (fmaxf(l, 0.f) - l * gt + log1pf(expf(-fabsf(l)))) * (0.01f / 512.f);
        // CST (weight 0.1)
        const float ddx = pam[pr * 3]     - trans[pr * 3];
        const float ddy = pam[pr * 3 + 1] - trans[pr * 3 + 1];
        const float ddz = pam[pr * 3 + 2] - trans[pr * 3 + 2];
        acc += sqrtf(ddx * ddx + ddy * ddy + ddz * ddz) * (0.1f / 512.f);
    }

    // KLD: 4096 elements, 16 per thread (weight -0.5 * 0.001 / 32)
    {
        float kl = 0.f;
        #pragma unroll
        for (int i = 0; i < 16; i++) {
            const int id = t * 16 + i;
            const float lv = logvar[id], m = mu[id];
            kl += 1.f + lv - m * m - expf(lv);
        }
        acc += kl * (-0.5f * 0.001f / 32.f);
    }

    // SPS: per-b mean over k of sfin, squared (weight 0.1)
    __syncthreads();
    if (t < 32) {
        float m = 0.f;
        #pragma unroll
        for (int kk2 = 0; kk2 < 16; kk2++) m += sfin[t * 16 + kk2];
        m *= (1.f / 16.f);
        acc += m * m * (0.1f / 32.f);
    }

    // block reduction of acc
    #pragma unroll
    for (int off = 16; off; off >>= 1)
        acc += __shfl_down_sync(0xffffffffu, acc, off);
    __syncthreads();
    if (lane == 0) srec[warp] = acc;
    __syncthreads();
    if (t == 0) {
        float s = 0.f;
        #pragma unroll
        for (int w = 0; w < 8; w++) s += srec[w];
        out[0] = s;
        g_count = 0;   // reset for next graph replay
    }
}

extern "C" void kernel_launch(void* const* d_in, const int* in_sizes, int n_in,
                              void* d_out, int out_size)
{
    const float* pc      = (const float*)d_in[0];
    const float* normals = (const float*)d_in[1];
    const float* randn   = (const float*)d_in[2];
    const float* scale   = (const float*)d_in[3];
    const float* shapes  = (const float*)d_in[4];
    const float* rotate  = (const float*)d_in[5];
    const float* pam     = (const float*)d_in[6];
    const float* assign  = (const float*)d_in[7];
    const float* exist   = (const float*)d_in[8];
    const float* mu      = (const float*)d_in[9];
    const float* logvar  = (const float*)d_in[10];
    const float* trans   = (const float*)d_in[11];
    float* out = (float*)d_out;

    loss_fused_kernel<<<GRIDA, 256>>>(pc, normals, randn, scale, shapes, rotate,
                                      pam, assign, exist, mu, logvar, trans, out);
}

// round 14
// speedup vs baseline: 3.0739x; 3.0739x over previous
#include <cuda_runtime.h>

#define Bn 32
#define Nn 4096
#define Kn 16
#define PTS 128                 // points per block
#define NBLK (Nn / PTS)         // 32 blocks per batch
#define GRIDA (Bn * NBLK)       // 1024 blocks x 256 threads

// Deterministic scratch (no allocations allowed)
__device__ float g_comb[GRIDA];             // rec + kld partial (pre-weighted)
__device__ float g_col_partial[GRIDA * Kn]; // assign column partials
__device__ unsigned int g_count = 0;

__device__ __forceinline__ float flog2(float x) {
    float y; asm("lg2.approx.f32 %0, %1;" : "=f"(y) : "f"(x)); return y;
}
__device__ __forceinline__ float fexp2(float x) {
    float y; asm("ex2.approx.f32 %0, %1;" : "=f"(y) : "f"(x)); return y;
}

__global__ __launch_bounds__(256, 5) void loss_fused_kernel(
    const float* __restrict__ pc, const float* __restrict__ normals,
    const float* __restrict__ randn, const float* __restrict__ scale,
    const float* __restrict__ shapes, const float* __restrict__ rotate,
    const float* __restrict__ pam, const float* __restrict__ assign,
    const float* __restrict__ exist, const float* __restrict__ mu,
    const float* __restrict__ logvar, const float* __restrict__ trans,
    float* __restrict__ out)
{
    // sP stride 20: [0-8]=R, [9-11]=scale, [12]=he0,[13]=he1,[14]=he01,[15-17]=ncc=-R^T mean
    __shared__ __align__(16) float sP[Kn * 20];
    __shared__ float sM[Kn * 3];                 // raw means (staging only)
    __shared__ __align__(16) float sA[PTS * 20]; // assign rows, stride-20
    __shared__ float scol2[256];
    __shared__ float srec[8];
    __shared__ float skld[4];
    __shared__ float sfin[512];
    __shared__ bool  isLast;

    const int blk   = blockIdx.x;
    const int b     = blk >> 5;          // batch
    const int t     = threadIdx.x;
    const int lane  = t & 31;
    const int warp  = t >> 5;
    const int nl    = t & (PTS - 1);     // local point id
    const int khalf = t >> 7;            // 0: k in [0,8), 1: k in [8,16)
    const int n     = (blk & 31) * PTS + nl;

    // Stage per-(b,k) parameters (he = 0.5 * shape exponent)
    if (t < 144) sP[(t / 9) * 20 + (t % 9)]      = rotate[b * 144 + t];
    if (t < 48)  sP[(t / 3) * 20 + 9 + (t % 3)]  = scale [b * 48  + t];
    if (t < 32)  sP[(t / 2) * 20 + 12 + (t & 1)] = 0.5f * shapes[b * 32 + t];
    if (t < 48)  sM[t]                           = pam   [b * 48  + t];

    // This thread's 8 assign weights -> registers, staged into sA (2x STS.128)
    float akr[8];
    {
        const float4* av = reinterpret_cast<const float4*>(assign)
                         + ((size_t)b * Nn + n) * 4 + khalf * 2;
        const float4 a0 = av[0], a1 = av[1];
        akr[0] = a0.x; akr[1] = a0.y; akr[2] = a0.z; akr[3] = a0.w;
        akr[4] = a1.x; akr[5] = a1.y; akr[6] = a1.z; akr[7] = a1.w;
        float4* dst = reinterpret_cast<float4*>(sA + nl * 20 + khalf * 8);
        dst[0] = a0; dst[1] = a1;
    }

    // KLD slice for this block (4 elements)
    if (t < 4) {
        const int id = blk * 4 + t;
        const float lv = logvar[id], m = mu[id];
        skld[t] = 1.f + lv - m * m - expf(lv);
    }
    __syncthreads();

    // ncc = -(R^T mean); he01 = he0 - he1
    if (t < 48) {
        const int k = t / 3, i = t % 3;
        const float* R = sP + k * 20;
        const float* m = sM + k * 3;
        sP[k * 20 + 15 + i] = -(R[i] * m[0] + R[3 + i] * m[1] + R[6 + i] * m[2]);
    } else if (t >= 64 && t < 80) {
        const int k = t - 64;
        sP[k * 20 + 14] = sP[k * 20 + 12] - sP[k * 20 + 13];
    }
    __syncthreads();

    // Point state (raw normals: argmax is scale-invariant; psi offset uses raw normals)
    const size_t pi = ((size_t)b * Nn + n) * 3;
    const float px = pc[pi], py = pc[pi + 1], pz = pc[pi + 2];
    const float nx = normals[pi], ny = normals[pi + 1], nz = normals[pi + 2];
    const float rn0 = randn[b * Nn + n] * 0.01f;   // noise weight on raw normal

    float rec = 0.f;

    #pragma unroll
    for (int kk = 0; kk < 8; kk++) {
        const int k = khalf * 8 + kk;
        const float4* Pv = reinterpret_cast<const float4*>(sP + k * 20);
        const float4 f0v = Pv[0];   // R0 R1 R2 R3
        const float4 f1v = Pv[1];   // R4 R5 R6 R7
        const float4 f2v = Pv[2];   // R8 s0 s1 s2
        const float4 f3v = Pv[3];   // he0 he1 he01 ncc0
        const float ncc1 = sP[k * 20 + 16];
        const float ncc2 = sP[k * 20 + 17];
        const float R0 = f0v.x, R1 = f0v.y, R2 = f0v.z, R3 = f0v.w;
        const float R4 = f1v.x, R5 = f1v.y, R6 = f1v.z, R7 = f1v.w;
        const float R8 = f2v.x, s0 = f2v.y, s1 = f2v.z, s2 = f2v.w;
        const float he0 = f3v.x, he1 = f3v.y, he01 = f3v.z, ncc0 = f3v.w;

        // pci = R^T pc - R^T mean
        const float c0 = fmaf(R0, px, fmaf(R3, py, fmaf(R6, pz, ncc0)));
        const float c1 = fmaf(R1, px, fmaf(R4, py, fmaf(R7, pz, ncc1)));
        const float c2 = fmaf(R2, px, fmaf(R5, py, fmaf(R8, pz, ncc2)));
        // w = R^T n_raw
        const float w0 = fmaf(R0, nx, fmaf(R3, ny, R6 * nz));
        const float w1 = fmaf(R1, nx, fmaf(R4, ny, R7 * nz));
        const float w2 = fmaf(R2, nx, fmaf(R5, ny, R8 * nz));
        // psi = pci + rn0 * w
        const float q0 = fmaf(rn0, w0, c0);
        const float q1 = fmaf(rn0, w1, c1);
        const float q2 = fmaf(rn0, w2, c2);

        // branchless argmax + override (ties -> lowest axis, matches jnp face order)
        const float a0 = fabsf(w0), a1 = fabsf(w1), a2 = fabsf(w2);
        const bool g0 = (a0 >= a1) & (a0 >= a2);
        const bool g1 = (!g0) & (a1 >= a2);
        const bool g2 = !(g0 | g1);
        const float p0 = g0 ? copysignf(s0, w0) : fminf(fmaxf(q0, -s0), s0);
        const float p1 = g1 ? copysignf(s1, w1) : fminf(fmaxf(q1, -s1), s1);
        const float p2 = g2 ? copysignf(s2, w2) : fminf(fmaxf(q2, -s2), s2);

        // log-domain superquadric surface point
        const float p0sq = fmaf(p0, p0, 1e-30f);
        const float p1sq = fmaf(p1, p1, 1e-30f);
        const float p2sq = fmaf(p2, p2, 1e-30f);
        const float r2   = p0sq + p1sq;
        const float rho2 = r2 + p2sq;

        const float Lr = flog2(r2);
        const float Lh = flog2(rho2);
        const float L0 = flog2(p0sq);
        const float L1 = flog2(p1sq);
        const float L2 = flog2(p2sq);

        const float hLh = he0 * Lh;
        const float u   = fmaf(he01, Lr, -hLh);
        const float X = copysignf(s0 * fexp2(fmaf(he1, L0, u)), p0);
        const float Y = copysignf(s1 * fexp2(fmaf(he1, L1, u)), p1);
        const float Z = copysignf(s2 * fexp2(fmaf(he0, L2, -hLh)), p2);

        const float dx = X - c0, dy = Y - c1, dz = Z - c2;
        rec = fmaf(fmaf(dx, dx, fmaf(dy, dy, dz * dz)), akr[kk], rec);
    }

    // --- block reductions (deterministic) ---
    #pragma unroll
    for (int off = 16; off; off >>= 1)
        rec += __shfl_down_sync(0xffffffffu, rec, off);
    if (lane == 0) srec[warp] = rec;

    // assign column sums from sA: thread t sums 8 rows of column (t&15)
    {
        const int kcol = t & 15, chunk = t >> 4;   // 16 chunks x 8 rows = 128 rows
        float csum = 0.f;
        #pragma unroll
        for (int i = 0; i < 8; i++)
            csum += sA[(chunk * 8 + i) * 20 + kcol];
        scol2[t] = csum;
    }
    __syncthreads();

    if (t == 0) {
        float s = 0.f;
        #pragma unroll
        for (int w = 0; w < 8; w++) s += srec[w];
        float kp = skld[0] + skld[1] + skld[2] + skld[3];
        g_comb[blk] = s * (1.0f / (32.f * 4096.f)) + kp * (-0.5f * 0.001f / 32.f);
    }
    if (t < Kn) {
        float s = 0.f;
        #pragma unroll
        for (int c = 0; c < 16; c++) s += scol2[t + c * 16];
        g_col_partial[blk * Kn + t] = s;
    }

    // --- last-block-done: fused final reduction ---
    __threadfence();
    __syncthreads();
    if (t == 0) {
        unsigned int v = atomicAdd(&g_count, 1u);
        isLast = (v == GRIDA - 1);
    }
    __syncthreads();
    if (!isLast) return;
    __threadfence();

    float acc = g_comb[t] + g_comb[t + 256] + g_comb[t + 512] + g_comb[t + 768];

    // cs for (b,k) pairs p = t and p = t+256
    float cs0 = 0.f, cs1 = 0.f;
    {
        const int b0 = t >> 4, b1 = (t + 256) >> 4, kc = t & 15;
        #pragma unroll
        for (int nb2 = 0; nb2 < 32; nb2++) {
            cs0 += g_col_partial[((b0 * 32 + nb2) << 4) + kc];
            cs1 += g_col_partial[((b1 * 32 + nb2) << 4) + kc];
        }
        sfin[t]       = sqrtf(cs0 * (1.f / 4096.f) + 0.01f);
        sfin[t + 256] = sqrtf(cs1 * (1.f / 4096.f) + 0.01f);
    }

    // EXT: BCE-with-logits for pairs t, t+256 (weight 0.01)
    {
        const float l0 = exist[t], l1 = exist[t + 256];
        const float gt0 = (cs0 > 24.f) ? 1.f : 0.f;
        const float gt1 = (cs1 > 24.f) ? 1.f : 0.f;
        const float e0v = fmaxf(l0, 0.f) - l0 * gt0 + log1pf(expf(-fabsf(l0)));
        const float e1v = fmaxf(l1, 0.f) - l1 * gt1 + log1pf(expf(-fabsf(l1)));
        acc += (e0v + e1v) * (0.01f / 512.f);
    }

    // CST: 512 (b,k) pairs, 2 per thread (weight 0.1)
    {
        const int p0i = t * 3, p1i = (t + 256) * 3;
        float dx0 = pam[p0i]     - trans[p0i];
        float dy0 = pam[p0i + 1] - trans[p0i + 1];
        float dz0 = pam[p0i + 2] - trans[p0i + 2];
        float dx1 = pam[p1i]     - trans[p1i];
        float dy1 = pam[p1i + 1] - trans[p1i + 1];
        float dz1 = pam[p1i + 2] - trans[p1i + 2];
        acc += (sqrtf(dx0 * dx0 + dy0 * dy0 + dz0 * dz0) +
                sqrtf(dx1 * dx1 + dy1 * dy1 + dz1 * dz1)) * (0.1f / 512.f);
    }

    // SPS: per-b mean over k of sfin, squared (weight 0.1)
    __syncthreads();
    if (t < 32) {
        float m = 0.f;
        #pragma unroll
        for (int kk2 = 0; kk2 < 16; kk2++) m += sfin[t * 16 + kk2];
        m *= (1.f / 16.f);
        acc += m * m * (0.1f / 32.f);
    }

    // block reduction of acc
    #pragma unroll
    for (int off = 16; off; off >>= 1)
        acc += __shfl_down_sync(0xffffffffu, acc, off);
    __syncthreads();
    if (lane == 0) srec[warp] = acc;
    __syncthreads();
    if (t == 0) {
        float s = 0.f;
        #pragma unroll
        for (int w = 0; w < 8; w++) s += srec[w];
        out[0] = s;
        g_count = 0;   // reset for next graph replay
    }
}

extern "C" void kernel_launch(void* const* d_in, const int* in_sizes, int n_in,
                              void* d_out, int out_size)
{
    const float* pc      = (const float*)d_in[0];
    const float* normals = (const float*)d_in[1];
    const float* randn   = (const float*)d_in[2];
    const float* scale   = (const float*)d_in[3];
    const float* shapes  = (const float*)d_in[4];
    const float* rotate  = (const float*)d_in[5];
    const float* pam     = (const float*)d_in[6];
    const float* assign  = (const float*)d_in[7];
    const float* exist   = (const float*)d_in[8];
    const float* mu      = (const float*)d_in[9];
    const float* logvar  = (const float*)d_in[10];
    const float* trans   = (const float*)d_in[11];
    float* out = (float*)d_out;

    loss_fused_kernel<<<GRIDA, 256>>>(pc, normals, randn, scale, shapes, rotate,
                                      pam, assign, exist, mu, logvar, trans, out);
}